// round 14
// baseline (speedup 1.0000x reference)
#include <cuda_runtime.h>
#include <math_constants.h>
#include <float.h>

// Problem constants (fixed by setup_inputs): B=64, Nt=64, Ns=4096, C=256,
// WIN=2, TOPK=3, GH=GW=4, 16 gabor kernels.
#define BMAX 64

__device__ float g_zmax[BMAX * 256];
__device__ float g_winsum[BMAX * 1024];
__device__ float g_gmap[16];
__device__ int   g_zready[BMAX];   // zero-init; 4 == batch's zmax published
__device__ int   g_wpass[BMAX];    // winsum blocks past the zmax wait
__device__ int   g_wdone[BMAX];    // winsum blocks finished (16 == batch done)
__device__ int   g_tpass[BMAX];    // tail blocks past the wait (3 == reset)
__device__ int   g_gdone;          // gabor map published
__device__ int   g_treset;         // global tail counter (resets g_gdone)

__device__ __forceinline__ float4 max4(float4 a, float4 b) {
    return make_float4(fmaxf(a.x, b.x), fmaxf(a.y, b.y),
                       fmaxf(a.z, b.z), fmaxf(a.w, b.w));
}

// better(v,i, w,j): strictly greater value, or equal value with lower index
// (matches jax.lax.top_k ordering).
__device__ __forceinline__ bool better(float v, int i, float w, int j) {
    return v > w || (v == w && i < j);
}
__device__ __forceinline__ void insert3(float v, int i, float* rv, int* ri) {
    if (better(v, i, rv[0], ri[0])) {
        rv[2] = rv[1]; ri[2] = ri[1];
        rv[1] = rv[0]; ri[1] = ri[0];
        rv[0] = v;     ri[0] = i;
    } else if (better(v, i, rv[1], ri[1])) {
        rv[2] = rv[1]; ri[2] = ri[1];
        rv[1] = v;     ri[1] = i;
    } else if (better(v, i, rv[2], ri[2])) {
        rv[2] = v;     ri[2] = i;
    }
}

// ---------------------------------------------------------------------------
// Single launch. grid = B*4 + 1 + B*16 + B*3, 256 threads.
// __launch_bounds__(256, 6) caps regs at ~42 so the STREAMING winsum blocks
// keep >=6 resident blocks/SM (R13 lesson: without the cap, the tail branch
// inflated the kernel to 88 regs and occupancy collapsed to 24%). The cold
// branches (zmax/gabor/tail) may spill to local — negligible, they are 449
// small blocks vs 1024 streaming ones.
// Block roles by bid (scheduler dispatches in bid order -> spinners, having
// the highest bids, only wait on already-dispatched work -> no deadlock):
//   [0, B*4)            zmax blocks     (publish slice, fence, tick)
//   B*4                 gabor block     (publish map, fence, flag)
//   (B*4, B*4+1+B*16)   winsum blocks   (spin on zmax, stream x, publish
//                                        winsums, fence, tick)
//   last B*3            tail blocks     (spin on batch winsums+gabor, top-3,
//                                        gather + upsample + scale + write)
// ---------------------------------------------------------------------------
__global__ void __launch_bounds__(256, 6) k_main(
        const float* __restrict__ x, const float* __restrict__ z,
        float* __restrict__ out, int B,
        const float* __restrict__ gth, const float* __restrict__ gsg,
        const float* __restrict__ glm, const float* __restrict__ gps,
        const float* __restrict__ ggm, const float* __restrict__ gwt) {
    int blk = blockIdx.x;
    int tid = threadIdx.x;
    const int WBASE = B * 4 + 1;
    const int TBASE = WBASE + B * 16;

    if (blk < B * 4) {   // ---------------- zmax block ----------------
        int b  = blk >> 2;
        int cg = blk & 3;              // 64-channel group
        int tg = tid >> 4;             // token group (4 tokens each)
        int c4 = tid & 15;             // float4 lane within group
        __shared__ float4 sm[16][16];

        const float4* zp = (const float4*)(z + ((size_t)b * 64 + tg * 4) * 256)
                           + cg * 16 + c4;
        float4 m = zp[0];
        m = max4(m, zp[64]);
        m = max4(m, zp[128]);
        m = max4(m, zp[192]);
        sm[tg][c4] = m;
        __syncthreads();

        if (tid < 16) {
            float4 r = sm[0][tid];
#pragma unroll
            for (int g = 1; g < 16; ++g) r = max4(r, sm[g][tid]);
            ((float4*)(g_zmax + b * 256 + cg * 64))[tid] = r;
            __threadfence();           // writer-side publish
        }
        __syncthreads();
        if (tid == 0) atomicAdd(&g_zready[b], 1);
        return;
    }

    if (blk == B * 4) {   // ---------------- gabor block ----------------
        int cell = tid >> 4;       // 0..15 -> (h,w)
        int k    = tid & 15;       // gabor kernel index
        int h = cell >> 2, w = cell & 3;
        float yy = (float)h - 1.5f;
        float xx = (float)w - 1.5f;
        float theta = gth[k] * (2.f * CUDART_PI_F);
        float ct = cosf(theta), st = sinf(theta);
        float xp =  xx * ct + yy * st;
        float yp = -xx * st + yy * ct;
        float sig = gsg[k] + 0.5f;
        float lmb = glm[k] + 0.5f;
        float gam = ggm[k];
        float env = expf(-(xp * xp + gam * gam * yp * yp) / (2.f * sig * sig));
        float car = cosf(2.f * CUDART_PI_F * xp / lmb + gps[k]);
        float term = gwt[k] * env * car;
#pragma unroll
        for (int o = 8; o > 0; o >>= 1)
            term += __shfl_down_sync(0xffffffffu, term, o, 16);
        if (k == 0) {
            g_gmap[cell] = 1.f + term;  // splat + x_up = x_up*(1+gmap)
            __threadfence();
        }
        __syncthreads();
        if (tid == 0) atomicExch(&g_gdone, 1);
        return;
    }

    if (blk < TBASE) {   // ---------------- winsum block ----------------
        int wblk = blk - WBASE;
        int b    = wblk >> 4;
        int whp  = wblk & 15;
        int warp = tid >> 5, lane = tid & 31;

        const float* x0 = x + (size_t)b * 4096 * 256
                            + (size_t)(whp * 2) * 128 * 256
                            + (size_t)warp * 4 * 2 * 256;
        const float* x1 = x0 + 128 * 256;      // second window row

        // Prefetch pixel-row-quad r=0: 16 float4 loads in flight.
        float4 va[2][4], vb[2][4];
#pragma unroll
        for (int q = 0; q < 4; ++q) {
            const float4* p0 = (const float4*)(x0 + q * 512);
            const float4* p1 = (const float4*)(x1 + q * 512);
            va[0][q] = __ldcs(p0 + lane);
            vb[0][q] = __ldcs(p0 + lane + 32);
            va[1][q] = __ldcs(p1 + lane);
            vb[1][q] = __ldcs(p1 + lane + 32);
        }

        // Wait for this batch's zmax (hidden under the prefetch latency).
        __shared__ float4 sz[64];
        if (tid == 0) {
            while (__ldcg(&g_zready[b]) < 4) __nanosleep(40);
            __threadfence();                   // acquire
        }
        __syncthreads();
        if (tid < 64) sz[tid] = __ldcg(((const float4*)(g_zmax + b * 256)) + tid);
        __syncthreads();
        if (tid == 0) {
            int old = atomicAdd(&g_wpass[b], 1);
            if (old == 15) { g_zready[b] = 0; g_wpass[b] = 0; }  // replay reset
        }

        float4 za = sz[lane], zb = sz[lane + 32];
        float acc[2][4];
#pragma unroll
        for (int wl = 0; wl < 2; ++wl)
#pragma unroll
            for (int q = 0; q < 4; ++q) {
                acc[wl][q]  = va[wl][q].x * za.x + va[wl][q].y * za.y
                            + va[wl][q].z * za.z + va[wl][q].w * za.w;
                acc[wl][q] += vb[wl][q].x * zb.x + vb[wl][q].y * zb.y
                            + vb[wl][q].z * zb.z + vb[wl][q].w * zb.w;
            }

#pragma unroll
        for (int r = 1; r < 4; ++r) {
            int off = ((r >> 1) * 64 + (r & 1)) * 256;  // rows s,s+1,s+64,s+65
#pragma unroll
            for (int q = 0; q < 4; ++q) {               // batch 16 loads
                const float4* p0 = (const float4*)(x0 + q * 512 + off);
                const float4* p1 = (const float4*)(x1 + q * 512 + off);
                va[0][q] = __ldcs(p0 + lane);
                vb[0][q] = __ldcs(p0 + lane + 32);
                va[1][q] = __ldcs(p1 + lane);
                vb[1][q] = __ldcs(p1 + lane + 32);
            }
#pragma unroll
            for (int wl = 0; wl < 2; ++wl)
#pragma unroll
                for (int q = 0; q < 4; ++q) {
                    acc[wl][q] += va[wl][q].x * za.x + va[wl][q].y * za.y
                                + va[wl][q].z * za.z + va[wl][q].w * za.w;
                    acc[wl][q] += vb[wl][q].x * zb.x + vb[wl][q].y * zb.y
                                + vb[wl][q].z * zb.z + vb[wl][q].w * zb.w;
                }
        }
#pragma unroll
        for (int wl = 0; wl < 2; ++wl)
#pragma unroll
            for (int q = 0; q < 4; ++q) {
                float a = acc[wl][q];
#pragma unroll
                for (int o = 16; o > 0; o >>= 1)
                    a += __shfl_down_sync(0xffffffffu, a, o);
                if (lane == 0)
                    g_winsum[b * 1024 + (whp * 2 + wl) * 32 + warp * 4 + q] = a;
            }
        if (lane == 0) __threadfence();        // writer-side publish
        __syncthreads();
        if (tid == 0) atomicAdd(&g_wdone[b], 1);
        return;
    }

    // ---------------- tail block ----------------
    int tblk = blk - TBASE;
    int b = tblk / 3;
    int t = tblk % 3;
    int warp = tid >> 5, lane = tid & 31;

    __shared__ float wv[8][3];
    __shared__ int   wi[8][3];
    __shared__ int   sidx[3];
    __shared__ float s_gmap[16];

    // Wait for this batch's winsums + the gabor map.
    if (tid == 0) {
        while (__ldcg(&g_wdone[b]) < 16 || __ldcg(&g_gdone) == 0)
            __nanosleep(60);
        __threadfence();                       // acquire
    }
    __syncthreads();
    if (tid == 0) {
        int old = atomicAdd(&g_tpass[b], 1);
        if (old == 2) { g_wdone[b] = 0; g_tpass[b] = 0; }     // replay reset
        int tot = atomicAdd(&g_treset, 1);
        if (tot == 3 * B - 1) { g_gdone = 0; g_treset = 0; }  // replay reset
    }
    if (tid < 16) s_gmap[tid] = __ldcg(&g_gmap[tid]);

    // Batch top-3 (__ldcg for cross-SM coherence).
    float rv[3] = {-FLT_MAX, -FLT_MAX, -FLT_MAX};
    int   ri[3] = {1 << 30, 1 << 30, 1 << 30};
#pragma unroll
    for (int k = 0; k < 4; ++k) {
        int i = tid + k * 256;
        insert3(__ldcg(&g_winsum[b * 1024 + i]), i, rv, ri);
    }
#pragma unroll
    for (int o = 16; o > 0; o >>= 1) {
        float ov[3]; int oi[3];
#pragma unroll
        for (int s = 0; s < 3; ++s) {
            ov[s] = __shfl_down_sync(0xffffffffu, rv[s], o);
            oi[s] = __shfl_down_sync(0xffffffffu, ri[s], o);
        }
#pragma unroll
        for (int s = 0; s < 3; ++s) insert3(ov[s], oi[s], rv, ri);
    }
    if (lane == 0) {
#pragma unroll
        for (int s = 0; s < 3; ++s) { wv[warp][s] = rv[s]; wi[warp][s] = ri[s]; }
    }
    __syncthreads();

    if (warp == 0) {
        float fv[3] = {-FLT_MAX, -FLT_MAX, -FLT_MAX};
        int   fi[3] = {1 << 30, 1 << 30, 1 << 30};
        if (lane < 8) {
#pragma unroll
            for (int s = 0; s < 3; ++s) { fv[s] = wv[lane][s]; fi[s] = wi[lane][s]; }
        }
#pragma unroll
        for (int o = 4; o > 0; o >>= 1) {
            float ov[3]; int oi[3];
#pragma unroll
            for (int s = 0; s < 3; ++s) {
                ov[s] = __shfl_down_sync(0xffffffffu, fv[s], o);
                oi[s] = __shfl_down_sync(0xffffffffu, fi[s], o);
            }
#pragma unroll
            for (int s = 0; s < 3; ++s) insert3(ov[s], oi[s], fv, fi);
        }
        if (lane == 0) {
#pragma unroll
            for (int s = 0; s < 3; ++s) sidx[s] = fi[s];
        }
    }
    __syncthreads();

    // jax half-pixel bilinear 2->4 weights: {1,0},{.75,.25},{.25,.75},{0,1}.
    const float wa[4] = {1.f, 0.75f, 0.25f, 0.f};
    const float wb[4] = {0.f, 0.25f, 0.75f, 1.f};
    int c = tid;

    int widx = sidx[t];
    int wh = widx >> 5, ww = widx & 31;
    const float* p = x + ((size_t)b * 4096 + wh * 128 + ww * 2) * 256 + c;
    float v00 = p[0];          // (i=0,j=0)
    float v01 = p[256];        // (i=0,j=1)
    float v10 = p[64 * 256];   // (i=1,j=0)
    float v11 = p[65 * 256];   // (i=1,j=1)

    float* ob = out + ((size_t)b * 48 + t * 16) * 256 + c;
#pragma unroll
    for (int gh = 0; gh < 4; ++gh) {
        float u0 = wa[gh] * v00 + wb[gh] * v10;  // interp along i (rows)
        float u1 = wa[gh] * v01 + wb[gh] * v11;
#pragma unroll
        for (int gw = 0; gw < 4; ++gw) {
            float val = wa[gw] * u0 + wb[gw] * u1;  // interp along j (cols)
            ob[(gh * 4 + gw) * 256] = val * s_gmap[gh * 4 + gw];
        }
    }
}

// ---------------------------------------------------------------------------
extern "C" void kernel_launch(void* const* d_in, const int* in_sizes, int n_in,
                              void* d_out, int out_size) {
    const float* z   = (const float*)d_in[0];
    const float* x   = (const float*)d_in[1];
    const float* gth = (const float*)d_in[2];
    const float* gsg = (const float*)d_in[3];
    const float* glm = (const float*)d_in[4];
    const float* gps = (const float*)d_in[5];
    const float* ggm = (const float*)d_in[6];
    const float* gwt = (const float*)d_in[7];
    float* out = (float*)d_out;

    int B = in_sizes[0] / (64 * 256);   // z is (B, 64, 256)

    int grid = B * 4 + 1 + B * 16 + B * 3;
    k_main<<<grid, 256>>>(x, z, out, B, gth, gsg, glm, gps, ggm, gwt);
}

// round 15
// speedup vs baseline: 1.9105x; 1.9105x over previous
#include <cuda_runtime.h>
#include <math_constants.h>
#include <float.h>

// Problem constants (fixed by setup_inputs): B=64, Nt=64, Ns=4096, C=256,
// WIN=2, TOPK=3, GH=GW=4, 16 gabor kernels.
#define BMAX 64

__device__ float g_zmax[BMAX * 256];
__device__ float g_winsum[BMAX * 1024];
__device__ float g_gmap[16];
__device__ int   g_zready[BMAX];   // zero-init; 4 == batch's zmax published
__device__ int   g_wpass[BMAX];    // winsum blocks past the zmax wait
__device__ int   g_wdone[BMAX];    // winsum blocks finished (16 == batch done)
__device__ int   g_tpass[BMAX];    // tail blocks past the wait (3 == reset)
__device__ int   g_gdone;          // gabor map published
__device__ int   g_treset;         // global tail counter (resets g_gdone)

__device__ __forceinline__ float4 max4(float4 a, float4 b) {
    return make_float4(fmaxf(a.x, b.x), fmaxf(a.y, b.y),
                       fmaxf(a.z, b.z), fmaxf(a.w, b.w));
}

// better(v,i, w,j): strictly greater value, or equal value with lower index
// (matches jax.lax.top_k ordering).
__device__ __forceinline__ bool better(float v, int i, float w, int j) {
    return v > w || (v == w && i < j);
}
__device__ __forceinline__ void insert3(float v, int i, float* rv, int* ri) {
    if (better(v, i, rv[0], ri[0])) {
        rv[2] = rv[1]; ri[2] = ri[1];
        rv[1] = rv[0]; ri[1] = ri[0];
        rv[0] = v;     ri[0] = i;
    } else if (better(v, i, rv[1], ri[1])) {
        rv[2] = rv[1]; ri[2] = ri[1];
        rv[1] = v;     ri[1] = i;
    } else if (better(v, i, rv[2], ri[2])) {
        rv[2] = v;     ri[2] = i;
    }
}

// ---------------------------------------------------------------------------
// Single launch. grid = B*4 + 1 + B*16 + B*3, 256 threads.
// __launch_bounds__(256, 4) -> 64-reg cap: the sweet spot. R14 proved a
// 40-reg cap spills the streaming path's 16-float4 load buffer to local
// (110us); R13 proved uncapped (88 regs) drops occupancy to 2 blocks/SM
// (54us). 64 regs = 4 blocks/SM, the geometry R11/R12's winsum ran at
// while sustaining 6.6 TB/s.
// Block roles by bid (scheduler dispatches in bid order -> spinners, having
// the highest bids, only wait on already-dispatched work -> no deadlock):
//   [0, B*4)            zmax blocks     (publish slice, fence, tick)
//   B*4                 gabor block     (publish map, fence, flag)
//   (B*4, B*4+1+B*16)   winsum blocks   (spin on zmax, stream x, publish
//                                        winsums, fence, tick)
//   last B*3            tail blocks     (spin on batch winsums+gabor, top-3,
//                                        gather + upsample + scale + write)
// ---------------------------------------------------------------------------
__global__ void __launch_bounds__(256, 4) k_main(
        const float* __restrict__ x, const float* __restrict__ z,
        float* __restrict__ out, int B,
        const float* __restrict__ gth, const float* __restrict__ gsg,
        const float* __restrict__ glm, const float* __restrict__ gps,
        const float* __restrict__ ggm, const float* __restrict__ gwt) {
    int blk = blockIdx.x;
    int tid = threadIdx.x;
    const int WBASE = B * 4 + 1;
    const int TBASE = WBASE + B * 16;

    if (blk < B * 4) {   // ---------------- zmax block ----------------
        int b  = blk >> 2;
        int cg = blk & 3;              // 64-channel group
        int tg = tid >> 4;             // token group (4 tokens each)
        int c4 = tid & 15;             // float4 lane within group
        __shared__ float4 sm[16][16];

        const float4* zp = (const float4*)(z + ((size_t)b * 64 + tg * 4) * 256)
                           + cg * 16 + c4;
        float4 m = zp[0];
        m = max4(m, zp[64]);
        m = max4(m, zp[128]);
        m = max4(m, zp[192]);
        sm[tg][c4] = m;
        __syncthreads();

        if (tid < 16) {
            float4 r = sm[0][tid];
#pragma unroll
            for (int g = 1; g < 16; ++g) r = max4(r, sm[g][tid]);
            ((float4*)(g_zmax + b * 256 + cg * 64))[tid] = r;
            __threadfence();           // writer-side publish
        }
        __syncthreads();
        if (tid == 0) atomicAdd(&g_zready[b], 1);
        return;
    }

    if (blk == B * 4) {   // ---------------- gabor block ----------------
        int cell = tid >> 4;       // 0..15 -> (h,w)
        int k    = tid & 15;       // gabor kernel index
        int h = cell >> 2, w = cell & 3;
        float yy = (float)h - 1.5f;
        float xx = (float)w - 1.5f;
        float theta = gth[k] * (2.f * CUDART_PI_F);
        float ct = cosf(theta), st = sinf(theta);
        float xp =  xx * ct + yy * st;
        float yp = -xx * st + yy * ct;
        float sig = gsg[k] + 0.5f;
        float lmb = glm[k] + 0.5f;
        float gam = ggm[k];
        float env = expf(-(xp * xp + gam * gam * yp * yp) / (2.f * sig * sig));
        float car = cosf(2.f * CUDART_PI_F * xp / lmb + gps[k]);
        float term = gwt[k] * env * car;
#pragma unroll
        for (int o = 8; o > 0; o >>= 1)
            term += __shfl_down_sync(0xffffffffu, term, o, 16);
        if (k == 0) {
            g_gmap[cell] = 1.f + term;  // splat + x_up = x_up*(1+gmap)
            __threadfence();
        }
        __syncthreads();
        if (tid == 0) atomicExch(&g_gdone, 1);
        return;
    }

    if (blk < TBASE) {   // ---------------- winsum block ----------------
        int wblk = blk - WBASE;
        int b    = wblk >> 4;
        int whp  = wblk & 15;
        int warp = tid >> 5, lane = tid & 31;

        const float* x0 = x + (size_t)b * 4096 * 256
                            + (size_t)(whp * 2) * 128 * 256
                            + (size_t)warp * 4 * 2 * 256;
        const float* x1 = x0 + 128 * 256;      // second window row

        // Prefetch pixel-row-quad r=0: 16 float4 loads in flight.
        float4 va[2][4], vb[2][4];
#pragma unroll
        for (int q = 0; q < 4; ++q) {
            const float4* p0 = (const float4*)(x0 + q * 512);
            const float4* p1 = (const float4*)(x1 + q * 512);
            va[0][q] = __ldcs(p0 + lane);
            vb[0][q] = __ldcs(p0 + lane + 32);
            va[1][q] = __ldcs(p1 + lane);
            vb[1][q] = __ldcs(p1 + lane + 32);
        }

        // Wait for this batch's zmax (hidden under the prefetch latency).
        __shared__ float4 sz[64];
        if (tid == 0) {
            while (__ldcg(&g_zready[b]) < 4) __nanosleep(40);
            __threadfence();                   // acquire
        }
        __syncthreads();
        if (tid < 64) sz[tid] = __ldcg(((const float4*)(g_zmax + b * 256)) + tid);
        __syncthreads();
        if (tid == 0) {
            int old = atomicAdd(&g_wpass[b], 1);
            if (old == 15) { g_zready[b] = 0; g_wpass[b] = 0; }  // replay reset
        }

        float4 za = sz[lane], zb = sz[lane + 32];
        float acc[2][4];
#pragma unroll
        for (int wl = 0; wl < 2; ++wl)
#pragma unroll
            for (int q = 0; q < 4; ++q) {
                acc[wl][q]  = va[wl][q].x * za.x + va[wl][q].y * za.y
                            + va[wl][q].z * za.z + va[wl][q].w * za.w;
                acc[wl][q] += vb[wl][q].x * zb.x + vb[wl][q].y * zb.y
                            + vb[wl][q].z * zb.z + vb[wl][q].w * zb.w;
            }

#pragma unroll
        for (int r = 1; r < 4; ++r) {
            int off = ((r >> 1) * 64 + (r & 1)) * 256;  // rows s,s+1,s+64,s+65
#pragma unroll
            for (int q = 0; q < 4; ++q) {               // batch 16 loads
                const float4* p0 = (const float4*)(x0 + q * 512 + off);
                const float4* p1 = (const float4*)(x1 + q * 512 + off);
                va[0][q] = __ldcs(p0 + lane);
                vb[0][q] = __ldcs(p0 + lane + 32);
                va[1][q] = __ldcs(p1 + lane);
                vb[1][q] = __ldcs(p1 + lane + 32);
            }
#pragma unroll
            for (int wl = 0; wl < 2; ++wl)
#pragma unroll
                for (int q = 0; q < 4; ++q) {
                    acc[wl][q] += va[wl][q].x * za.x + va[wl][q].y * za.y
                                + va[wl][q].z * za.z + va[wl][q].w * za.w;
                    acc[wl][q] += vb[wl][q].x * zb.x + vb[wl][q].y * zb.y
                                + vb[wl][q].z * zb.z + vb[wl][q].w * zb.w;
                }
        }
#pragma unroll
        for (int wl = 0; wl < 2; ++wl)
#pragma unroll
            for (int q = 0; q < 4; ++q) {
                float a = acc[wl][q];
#pragma unroll
                for (int o = 16; o > 0; o >>= 1)
                    a += __shfl_down_sync(0xffffffffu, a, o);
                if (lane == 0)
                    g_winsum[b * 1024 + (whp * 2 + wl) * 32 + warp * 4 + q] = a;
            }
        if (lane == 0) __threadfence();        // writer-side publish
        __syncthreads();
        if (tid == 0) atomicAdd(&g_wdone[b], 1);
        return;
    }

    // ---------------- tail block ----------------
    int tblk = blk - TBASE;
    int b = tblk / 3;
    int t = tblk % 3;
    int warp = tid >> 5, lane = tid & 31;

    __shared__ float wv[8][3];
    __shared__ int   wi[8][3];
    __shared__ int   sidx[3];
    __shared__ float s_gmap[16];

    // Wait for this batch's winsums + the gabor map.
    if (tid == 0) {
        while (__ldcg(&g_wdone[b]) < 16 || __ldcg(&g_gdone) == 0)
            __nanosleep(60);
        __threadfence();                       // acquire
    }
    __syncthreads();
    if (tid == 0) {
        int old = atomicAdd(&g_tpass[b], 1);
        if (old == 2) { g_wdone[b] = 0; g_tpass[b] = 0; }     // replay reset
        int tot = atomicAdd(&g_treset, 1);
        if (tot == 3 * B - 1) { g_gdone = 0; g_treset = 0; }  // replay reset
    }
    if (tid < 16) s_gmap[tid] = __ldcg(&g_gmap[tid]);

    // Batch top-3 (__ldcg for cross-SM coherence).
    float rv[3] = {-FLT_MAX, -FLT_MAX, -FLT_MAX};
    int   ri[3] = {1 << 30, 1 << 30, 1 << 30};
#pragma unroll
    for (int k = 0; k < 4; ++k) {
        int i = tid + k * 256;
        insert3(__ldcg(&g_winsum[b * 1024 + i]), i, rv, ri);
    }
#pragma unroll
    for (int o = 16; o > 0; o >>= 1) {
        float ov[3]; int oi[3];
#pragma unroll
        for (int s = 0; s < 3; ++s) {
            ov[s] = __shfl_down_sync(0xffffffffu, rv[s], o);
            oi[s] = __shfl_down_sync(0xffffffffu, ri[s], o);
        }
#pragma unroll
        for (int s = 0; s < 3; ++s) insert3(ov[s], oi[s], rv, ri);
    }
    if (lane == 0) {
#pragma unroll
        for (int s = 0; s < 3; ++s) { wv[warp][s] = rv[s]; wi[warp][s] = ri[s]; }
    }
    __syncthreads();

    if (warp == 0) {
        float fv[3] = {-FLT_MAX, -FLT_MAX, -FLT_MAX};
        int   fi[3] = {1 << 30, 1 << 30, 1 << 30};
        if (lane < 8) {
#pragma unroll
            for (int s = 0; s < 3; ++s) { fv[s] = wv[lane][s]; fi[s] = wi[lane][s]; }
        }
#pragma unroll
        for (int o = 4; o > 0; o >>= 1) {
            float ov[3]; int oi[3];
#pragma unroll
            for (int s = 0; s < 3; ++s) {
                ov[s] = __shfl_down_sync(0xffffffffu, fv[s], o);
                oi[s] = __shfl_down_sync(0xffffffffu, fi[s], o);
            }
#pragma unroll
            for (int s = 0; s < 3; ++s) insert3(ov[s], oi[s], fv, fi);
        }
        if (lane == 0) {
#pragma unroll
            for (int s = 0; s < 3; ++s) sidx[s] = fi[s];
        }
    }
    __syncthreads();

    // jax half-pixel bilinear 2->4 weights: {1,0},{.75,.25},{.25,.75},{0,1}.
    const float wa[4] = {1.f, 0.75f, 0.25f, 0.f};
    const float wb[4] = {0.f, 0.25f, 0.75f, 1.f};
    int c = tid;

    int widx = sidx[t];
    int wh = widx >> 5, ww = widx & 31;
    const float* p = x + ((size_t)b * 4096 + wh * 128 + ww * 2) * 256 + c;
    float v00 = p[0];          // (i=0,j=0)
    float v01 = p[256];        // (i=0,j=1)
    float v10 = p[64 * 256];   // (i=1,j=0)
    float v11 = p[65 * 256];   // (i=1,j=1)

    float* ob = out + ((size_t)b * 48 + t * 16) * 256 + c;
#pragma unroll
    for (int gh = 0; gh < 4; ++gh) {
        float u0 = wa[gh] * v00 + wb[gh] * v10;  // interp along i (rows)
        float u1 = wa[gh] * v01 + wb[gh] * v11;
#pragma unroll
        for (int gw = 0; gw < 4; ++gw) {
            float val = wa[gw] * u0 + wb[gw] * u1;  // interp along j (cols)
            ob[(gh * 4 + gw) * 256] = val * s_gmap[gh * 4 + gw];
        }
    }
}

// ---------------------------------------------------------------------------
extern "C" void kernel_launch(void* const* d_in, const int* in_sizes, int n_in,
                              void* d_out, int out_size) {
    const float* z   = (const float*)d_in[0];
    const float* x   = (const float*)d_in[1];
    const float* gth = (const float*)d_in[2];
    const float* gsg = (const float*)d_in[3];
    const float* glm = (const float*)d_in[4];
    const float* gps = (const float*)d_in[5];
    const float* ggm = (const float*)d_in[6];
    const float* gwt = (const float*)d_in[7];
    float* out = (float*)d_out;

    int B = in_sizes[0] / (64 * 256);   // z is (B, 64, 256)

    int grid = B * 4 + 1 + B * 16 + B * 3;
    k_main<<<grid, 256>>>(x, z, out, B, gth, gsg, glm, gps, ggm, gwt);
}

// round 16
// speedup vs baseline: 2.1399x; 1.1200x over previous
#include <cuda_runtime.h>
#include <math_constants.h>
#include <float.h>

// Problem constants (fixed by setup_inputs): B=64, Nt=64, Ns=4096, C=256,
// WIN=2, TOPK=3, GH=GW=4, 16 gabor kernels.
#define BMAX 64

__device__ float g_zmax[BMAX * 256];
__device__ float g_winsum[BMAX * 1024];
__device__ float g_gmap[16];
__device__ int   g_zready[BMAX];   // zero-init; 4 == batch's zmax published
__device__ int   g_wpass[BMAX];    // winsum blocks past the zmax wait (16 -> reset)

__device__ __forceinline__ float4 max4(float4 a, float4 b) {
    return make_float4(fmaxf(a.x, b.x), fmaxf(a.y, b.y),
                       fmaxf(a.z, b.z), fmaxf(a.w, b.w));
}

// better(v,i, w,j): strictly greater value, or equal value with lower index
// (matches jax.lax.top_k ordering).
__device__ __forceinline__ bool better(float v, int i, float w, int j) {
    return v > w || (v == w && i < j);
}
__device__ __forceinline__ void insert3(float v, int i, float* rv, int* ri) {
    if (better(v, i, rv[0], ri[0])) {
        rv[2] = rv[1]; ri[2] = ri[1];
        rv[1] = rv[0]; ri[1] = ri[0];
        rv[0] = v;     ri[0] = i;
    } else if (better(v, i, rv[1], ri[1])) {
        rv[2] = rv[1]; ri[2] = ri[1];
        rv[1] = v;     ri[1] = i;
    } else if (better(v, i, rv[2], ri[2])) {
        rv[2] = v;     ri[2] = i;
    }
}

// ---------------------------------------------------------------------------
// Main kernel. grid = B*16 + 1. NO dedicated zmax blocks (R16 change): the
// first 4 winsum blocks of each batch (whp < 4) compute + publish their
// batch's zmax slice BEFORE their prefetch (zmax temps are dead before the
// load buffer goes live -> no register growth; z is still read exactly once).
// This frees all wave-1 slots for x streaming and shortens the spin.
//   blk == B*16 : gabor block (fully parallel 16 cells x 16 kernels).
//   blk <  B*16 : winsum block, b = blk>>4, whp = blk&15 (window rows
//                 2whp, 2whp+1). Prefetch 16 float4 -> spin on g_zready[b]==4
//                 (publishers are same-batch LOWER bids -> dispatched first ->
//                 no deadlock; invariant validated in R12) -> FMA stream.
// winsum[b, wh*32+ww] = sum_{i,j} dot(x[b,(2wh+i)*64+2ww+j,:], zmax[b,:])
// ---------------------------------------------------------------------------
__global__ void __launch_bounds__(256) k_main(
        const float* __restrict__ x, const float* __restrict__ z, int B,
        const float* __restrict__ gth, const float* __restrict__ gsg,
        const float* __restrict__ glm, const float* __restrict__ gps,
        const float* __restrict__ ggm, const float* __restrict__ gwt) {
    int blk = blockIdx.x;
    int tid = threadIdx.x;

    if (blk == B * 16) {   // ---------------- gabor block ----------------
        int cell = tid >> 4;       // 0..15 -> (h,w)
        int k    = tid & 15;       // gabor kernel index
        int h = cell >> 2, w = cell & 3;
        float yy = (float)h - 1.5f;
        float xx = (float)w - 1.5f;
        float theta = gth[k] * (2.f * CUDART_PI_F);
        float ct = cosf(theta), st = sinf(theta);
        float xp =  xx * ct + yy * st;
        float yp = -xx * st + yy * ct;
        float sig = gsg[k] + 0.5f;
        float lmb = glm[k] + 0.5f;
        float gam = ggm[k];
        float env = expf(-(xp * xp + gam * gam * yp * yp) / (2.f * sig * sig));
        float car = cosf(2.f * CUDART_PI_F * xp / lmb + gps[k]);
        float term = gwt[k] * env * car;
#pragma unroll
        for (int o = 8; o > 0; o >>= 1)
            term += __shfl_down_sync(0xffffffffu, term, o, 16);
        if (k == 0) g_gmap[cell] = 1.f + term;  // splat + x_up = x_up*(1+gmap)
        return;
    }

    int b   = blk >> 4;
    int whp = blk & 15;
    int warp = tid >> 5, lane = tid & 31;
    __shared__ float4 szslice[16][16];
    __shared__ float4 sz[64];

    // --- publishers: compute zmax slice cg = whp (64 channels) ---
    if (whp < 4) {
        int tg = tid >> 4;             // token group (4 tokens each)
        int c4 = tid & 15;             // float4 lane within the 64-ch slice
        const float4* zp = (const float4*)(z + ((size_t)b * 64 + tg * 4) * 256)
                           + whp * 16 + c4;
        float4 m = max4(max4(zp[0], zp[64]), max4(zp[128], zp[192]));
        szslice[tg][c4] = m;
        __syncthreads();
        if (tid < 16) {
            float4 r = szslice[0][tid];
#pragma unroll
            for (int g = 1; g < 16; ++g) r = max4(r, szslice[g][tid]);
            ((float4*)(g_zmax + b * 256 + whp * 64))[tid] = r;
            __threadfence();           // writer-side publish
        }
        __syncthreads();
        if (tid == 0) atomicAdd(&g_zready[b], 1);
    }

    const float* x0 = x + (size_t)b * 4096 * 256
                        + (size_t)(whp * 2) * 128 * 256
                        + (size_t)warp * 4 * 2 * 256;
    const float* x1 = x0 + 128 * 256;      // second window row

    // Prefetch pixel-row-quad r=0: 16 float4 loads in flight.
    float4 va[2][4], vb[2][4];
#pragma unroll
    for (int q = 0; q < 4; ++q) {
        const float4* p0 = (const float4*)(x0 + q * 512);
        const float4* p1 = (const float4*)(x1 + q * 512);
        va[0][q] = __ldcs(p0 + lane);
        vb[0][q] = __ldcs(p0 + lane + 32);
        va[1][q] = __ldcs(p1 + lane);
        vb[1][q] = __ldcs(p1 + lane + 32);
    }

    // Wait for this batch's zmax (hidden under the prefetch latency).
    if (tid == 0) {
        while (__ldcg(&g_zready[b]) < 4) __nanosleep(40);
        __threadfence();                   // acquire
    }
    __syncthreads();
    if (tid < 64) sz[tid] = __ldcg(((const float4*)(g_zmax + b * 256)) + tid);
    __syncthreads();
    if (tid == 0) {
        int old = atomicAdd(&g_wpass[b], 1);
        if (old == 15) { g_zready[b] = 0; g_wpass[b] = 0; }  // replay reset
    }

    float4 za = sz[lane], zb = sz[lane + 32];
    float acc[2][4];
#pragma unroll
    for (int wl = 0; wl < 2; ++wl)
#pragma unroll
        for (int q = 0; q < 4; ++q) {
            acc[wl][q]  = va[wl][q].x * za.x + va[wl][q].y * za.y
                        + va[wl][q].z * za.z + va[wl][q].w * za.w;
            acc[wl][q] += vb[wl][q].x * zb.x + vb[wl][q].y * zb.y
                        + vb[wl][q].z * zb.z + vb[wl][q].w * zb.w;
        }

#pragma unroll
    for (int r = 1; r < 4; ++r) {
        int off = ((r >> 1) * 64 + (r & 1)) * 256;   // rows s, s+1, s+64, s+65
#pragma unroll
        for (int q = 0; q < 4; ++q) {                // batch 16 loads
            const float4* p0 = (const float4*)(x0 + q * 512 + off);
            const float4* p1 = (const float4*)(x1 + q * 512 + off);
            va[0][q] = __ldcs(p0 + lane);
            vb[0][q] = __ldcs(p0 + lane + 32);
            va[1][q] = __ldcs(p1 + lane);
            vb[1][q] = __ldcs(p1 + lane + 32);
        }
#pragma unroll
        for (int wl = 0; wl < 2; ++wl)
#pragma unroll
            for (int q = 0; q < 4; ++q) {
                acc[wl][q] += va[wl][q].x * za.x + va[wl][q].y * za.y
                            + va[wl][q].z * za.z + va[wl][q].w * za.w;
                acc[wl][q] += vb[wl][q].x * zb.x + vb[wl][q].y * zb.y
                            + vb[wl][q].z * zb.z + vb[wl][q].w * zb.w;
            }
    }
#pragma unroll
    for (int wl = 0; wl < 2; ++wl)
#pragma unroll
        for (int q = 0; q < 4; ++q) {
            float a = acc[wl][q];
#pragma unroll
            for (int o = 16; o > 0; o >>= 1)
                a += __shfl_down_sync(0xffffffffu, a, o);
            if (lane == 0)
                g_winsum[b * 1024 + (whp * 2 + wl) * 32 + warp * 4 + q] = a;
        }
}

// ---------------------------------------------------------------------------
// Tail (exact R8/R12 config — best measured). grid = B*3, 256 threads.
// Block (b, t): redundant batch top-3 (warp-shuffle triple merge, 2 barriers),
// then handles window rank t: gather, bilinear 2->4, (1+gmap) scale, write.
// jax half-pixel bilinear 2->4 weights: {1,0},{.75,.25},{.25,.75},{0,1}.
// ---------------------------------------------------------------------------
__global__ void __launch_bounds__(256) k_tail(const float* __restrict__ x,
                                              float* __restrict__ out) {
    int b = blockIdx.x / 3;
    int t = blockIdx.x % 3;
    __shared__ float wv[8][3];
    __shared__ int   wi[8][3];
    __shared__ int   sidx[3];
    __shared__ float s_gmap[16];
    int tid = threadIdx.x;
    int warp = tid >> 5, lane = tid & 31;

    if (tid < 16) s_gmap[tid] = g_gmap[tid];

    float rv[3] = {-FLT_MAX, -FLT_MAX, -FLT_MAX};
    int   ri[3] = {1 << 30, 1 << 30, 1 << 30};
#pragma unroll
    for (int k = 0; k < 4; ++k) {
        int i = tid + k * 256;
        insert3(__ldg(&g_winsum[b * 1024 + i]), i, rv, ri);
    }
#pragma unroll
    for (int o = 16; o > 0; o >>= 1) {
        float ov[3]; int oi[3];
#pragma unroll
        for (int s = 0; s < 3; ++s) {
            ov[s] = __shfl_down_sync(0xffffffffu, rv[s], o);
            oi[s] = __shfl_down_sync(0xffffffffu, ri[s], o);
        }
#pragma unroll
        for (int s = 0; s < 3; ++s) insert3(ov[s], oi[s], rv, ri);
    }
    if (lane == 0) {
#pragma unroll
        for (int s = 0; s < 3; ++s) { wv[warp][s] = rv[s]; wi[warp][s] = ri[s]; }
    }
    __syncthreads();

    if (warp == 0) {
        float fv[3] = {-FLT_MAX, -FLT_MAX, -FLT_MAX};
        int   fi[3] = {1 << 30, 1 << 30, 1 << 30};
        if (lane < 8) {
#pragma unroll
            for (int s = 0; s < 3; ++s) { fv[s] = wv[lane][s]; fi[s] = wi[lane][s]; }
        }
#pragma unroll
        for (int o = 4; o > 0; o >>= 1) {
            float ov[3]; int oi[3];
#pragma unroll
            for (int s = 0; s < 3; ++s) {
                ov[s] = __shfl_down_sync(0xffffffffu, fv[s], o);
                oi[s] = __shfl_down_sync(0xffffffffu, fi[s], o);
            }
#pragma unroll
            for (int s = 0; s < 3; ++s) insert3(ov[s], oi[s], fv, fi);
        }
        if (lane == 0) {
#pragma unroll
            for (int s = 0; s < 3; ++s) sidx[s] = fi[s];
        }
    }
    __syncthreads();

    const float wa[4] = {1.f, 0.75f, 0.25f, 0.f};
    const float wb[4] = {0.f, 0.25f, 0.75f, 1.f};
    int c = tid;

    int widx = sidx[t];
    int wh = widx >> 5, ww = widx & 31;
    const float* p = x + ((size_t)b * 4096 + wh * 128 + ww * 2) * 256 + c;
    float v00 = p[0];          // (i=0,j=0)
    float v01 = p[256];        // (i=0,j=1)
    float v10 = p[64 * 256];   // (i=1,j=0)
    float v11 = p[65 * 256];   // (i=1,j=1)

    float* ob = out + ((size_t)b * 48 + t * 16) * 256 + c;
#pragma unroll
    for (int gh = 0; gh < 4; ++gh) {
        float u0 = wa[gh] * v00 + wb[gh] * v10;  // interp along i (rows)
        float u1 = wa[gh] * v01 + wb[gh] * v11;
#pragma unroll
        for (int gw = 0; gw < 4; ++gw) {
            float val = wa[gw] * u0 + wb[gw] * u1;  // interp along j (cols)
            ob[(gh * 4 + gw) * 256] = val * s_gmap[gh * 4 + gw];
        }
    }
}

// ---------------------------------------------------------------------------
extern "C" void kernel_launch(void* const* d_in, const int* in_sizes, int n_in,
                              void* d_out, int out_size) {
    const float* z   = (const float*)d_in[0];
    const float* x   = (const float*)d_in[1];
    const float* gth = (const float*)d_in[2];
    const float* gsg = (const float*)d_in[3];
    const float* glm = (const float*)d_in[4];
    const float* gps = (const float*)d_in[5];
    const float* ggm = (const float*)d_in[6];
    const float* gwt = (const float*)d_in[7];
    float* out = (float*)d_out;

    int B = in_sizes[0] / (64 * 256);   // z is (B, 64, 256)

    k_main<<<B * 16 + 1, 256>>>(x, z, B, gth, gsg, glm, gps, ggm, gwt);
    k_tail<<<B * 3,      256>>>(x, out);
}